// round 4
// baseline (speedup 1.0000x reference)
#include <cuda_runtime.h>
#include <cuda_bf16.h>
#include <math.h>

#define G_   512
#define NPG  90
#define NN   (G_ * NPG)      // 46080
#define DEG  20
#define EE   (NN * DEG)      // 921600
#define F_IN 90
#define HH   64
#define KK   70
#define PDIM (KK * HH)       // 4480

// ---------------- device scratch (static, no allocations) ----------------
__device__ float g_t[NN * HH];      // X @ Wl  (message features)
__device__ float g_self[NN * HH];   // X @ Wr + b (self features)
__device__ float g_r1[NN * HH];     // relu(h1)
__device__ float g_h2[NN * HH];     // conv2 output
__device__ float g_p[G_ * PDIM];    // pooled features
__device__ int   g_cnt[NN];
__device__ int   g_cur[NN];
__device__ int   g_off[NN + 1];
__device__ int   g_eidx[EE];

// ---------------- CSR build ----------------
__global__ void zero_kernel() {
    int i = blockIdx.x * blockDim.x + threadIdx.x;
    if (i < NN) { g_cnt[i] = 0; g_cur[i] = 0; }
}

__global__ void count_kernel(const int* __restrict__ dst) {
    int e = blockIdx.x * blockDim.x + threadIdx.x;
    if (e < EE) {
        int d = dst[e];
        if ((unsigned)d < NN) atomicAdd(&g_cnt[d], 1);
    }
}

// single block, 1024 threads, 45 elems/thread (46080 = 1024*45)
__global__ void scan_kernel() {
    __shared__ int sums[1024];
    int tid = threadIdx.x;
    int base = tid * 45;
    int run = 0;
    #pragma unroll 5
    for (int i = 0; i < 45; i++) run += g_cnt[base + i];
    sums[tid] = run;
    __syncthreads();
    for (int d = 1; d < 1024; d <<= 1) {
        int v = 0;
        if (tid >= d) v = sums[tid - d];
        __syncthreads();
        if (tid >= d) sums[tid] += v;
        __syncthreads();
    }
    int pre = (tid == 0) ? 0 : sums[tid - 1];
    #pragma unroll 5
    for (int i = 0; i < 45; i++) {
        g_off[base + i] = pre;
        pre += g_cnt[base + i];
    }
    if (tid == 1023) g_off[NN] = pre;
}

__global__ void fill_kernel(const int* __restrict__ src,
                            const int* __restrict__ dst) {
    int e = blockIdx.x * blockDim.x + threadIdx.x;
    if (e < EE) {
        int d = dst[e];
        int s = src[e];
        if ((unsigned)d < NN && (unsigned)s < NN) {
            int p = atomicAdd(&g_cur[d], 1);
            g_eidx[g_off[d] + p] = s;
        }
    }
}

// ---------------- fused dual GEMM: T = X@Wl ; S = X@Wr + b ----------------
// blockDim 256; 128 rows per block (4 passes of 32 rows = 4 rowgroups x 8 rows)
template <int K, bool USE_R1>
__global__ void gemm_dual(const float* __restrict__ Xin,
                          const float* __restrict__ Wl,
                          const float* __restrict__ Wr,
                          const float* __restrict__ bias) {
    extern __shared__ float smem[];
    float* Ws = smem;               // [K][128]
    float* Xs = smem + K * 128;     // [32][K]
    const float* X = USE_R1 ? g_r1 : Xin;

    int t = threadIdx.x;
    int c = t & 63;
    int rg = t >> 6;                // 0..3

    for (int idx = t; idx < K * 128; idx += 256) {
        int k = idx >> 7, cc = idx & 127;
        Ws[idx] = (cc < 64) ? Wl[k * 64 + cc] : Wr[k * 64 + (cc - 64)];
    }
    __syncthreads();

    int rowBase = blockIdx.x * 128;
    float bv = bias[c];

    for (int p = 0; p < 4; p++) {
        int r0 = rowBase + p * 32;
        for (int idx = t; idx < 32 * K; idx += 256) {
            int row = idx / K, k = idx - row * K;
            Xs[row * K + k] = X[(r0 + row) * K + k];
        }
        __syncthreads();

        float acc0[8], acc1[8];
        #pragma unroll
        for (int i = 0; i < 8; i++) { acc0[i] = 0.f; acc1[i] = 0.f; }

        const float* xb = Xs + (rg * 8) * K;
        #pragma unroll 2
        for (int k = 0; k < K; k++) {
            float w0 = Ws[k * 128 + c];
            float w1 = Ws[k * 128 + 64 + c];
            #pragma unroll
            for (int i = 0; i < 8; i++) {
                float xv = xb[i * K + k];
                acc0[i] = fmaf(xv, w0, acc0[i]);
                acc1[i] = fmaf(xv, w1, acc1[i]);
            }
        }
        #pragma unroll
        for (int i = 0; i < 8; i++) {
            int row = r0 + rg * 8 + i;
            g_t[row * 64 + c]    = acc0[i];
            g_self[row * 64 + c] = acc1[i] + bv;
        }
        __syncthreads();
    }
}

// ---------------- aggregation: h = mean_csr(t) + self ----------------
// block = graph, 256 threads (8 warps), smem-staged 90x64 message rows
// FIRST=true : write h1 -> out_h (x_train region) and relu(h1) -> g_r1
// FIRST=false: write h2 -> g_h2 (out_h ignored)
template <bool FIRST>
__global__ void aggregate(float* __restrict__ out_h) {
    __shared__ float ts[NPG * HH];   // 23040 B
    int g = blockIdx.x;
    int base = g * NPG;
    int t = threadIdx.x;

    for (int i = t; i < NPG * HH; i += 256)
        ts[i] = g_t[base * HH + i];
    __syncthreads();

    int wid = t >> 5, lane = t & 31;
    for (int n = wid; n < NPG; n += 8) {
        int node = base + n;
        int s0 = g_off[node], s1 = g_off[node + 1];
        float a0 = 0.f, a1 = 0.f;
        for (int j = s0; j < s1; j++) {
            int sl = g_eidx[j] - base;
            a0 += ts[sl * 64 + lane];
            a1 += ts[sl * 64 + 32 + lane];
        }
        int cnt = s1 - s0;
        float inv = 1.0f / (float)max(cnt, 1);
        float h0 = fmaf(a0, inv, g_self[node * 64 + lane]);
        float h1 = fmaf(a1, inv, g_self[node * 64 + 32 + lane]);
        if (FIRST) {
            out_h[node * 64 + lane]      = h0;
            out_h[node * 64 + 32 + lane] = h1;
            g_r1[node * 64 + lane]      = fmaxf(h0, 0.f);
            g_r1[node * 64 + 32 + lane] = fmaxf(h1, 0.f);
        } else {
            g_h2[node * 64 + lane]      = h0;
            g_h2[node * 64 + 32 + lane] = h1;
        }
    }
}

// ---------------- sort pool (stable desc by channel 63, top-70) ----------------
__global__ void pool_kernel() {
    __shared__ float key[NPG];
    __shared__ int order[KK];
    int g = blockIdx.x;
    int base = g * NPG;
    int t = threadIdx.x;

    if (t < NPG) key[t] = g_h2[(base + t) * 64 + 63];
    __syncthreads();
    if (t < NPG) {
        float kv = key[t];
        int rank = 0;
        #pragma unroll 6
        for (int j = 0; j < NPG; j++) {
            float kj = key[j];
            rank += (kj > kv) || (kj == kv && j < t);
        }
        if (rank < KK) order[rank] = t;
    }
    __syncthreads();
    for (int idx = t; idx < PDIM; idx += 256) {
        int r = idx >> 6, f = idx & 63;
        g_p[g * PDIM + idx] = g_h2[(base + order[r]) * 64 + f];
    }
}

// ---------------- MLP: P[512,4480]@Wl1[4480,64]+bl1 -> @Wl2[64]+bl2 -> sigmoid ----------------
__global__ void mlp_kernel(const float* __restrict__ Wl1,
                           const float* __restrict__ bl1,
                           const float* __restrict__ Wl2,
                           const float* __restrict__ bl2,
                           float* __restrict__ out) {
    __shared__ char sbuf[32768];
    float* Ps = (float*)sbuf;            // [128][32] = 16 KB
    float* Ws = (float*)(sbuf + 16384);  // [32][64]  =  8 KB

    int t = threadIdx.x;
    int c0 = (t & 15) * 4;
    int g0 = (t >> 4) * 8;
    int gbase = blockIdx.x * 128;

    float acc[8][4];
    #pragma unroll
    for (int i = 0; i < 8; i++)
        #pragma unroll
        for (int j = 0; j < 4; j++) acc[i][j] = 0.f;

    for (int kc = 0; kc < PDIM / 32; kc++) {
        for (int idx = t; idx < 128 * 32; idx += 256) {
            int g = idx >> 5, kk = idx & 31;
            Ps[idx] = g_p[(gbase + g) * PDIM + kc * 32 + kk];
        }
        for (int idx = t; idx < 32 * 64; idx += 256) {
            int kk = idx >> 6, c = idx & 63;
            Ws[idx] = Wl1[(kc * 32 + kk) * 64 + c];
        }
        __syncthreads();
        #pragma unroll 4
        for (int kk = 0; kk < 32; kk++) {
            float w0 = Ws[kk * 64 + c0 + 0];
            float w1 = Ws[kk * 64 + c0 + 1];
            float w2 = Ws[kk * 64 + c0 + 2];
            float w3 = Ws[kk * 64 + c0 + 3];
            #pragma unroll
            for (int gi = 0; gi < 8; gi++) {
                float pv = Ps[(g0 + gi) * 32 + kk];
                acc[gi][0] = fmaf(pv, w0, acc[gi][0]);
                acc[gi][1] = fmaf(pv, w1, acc[gi][1]);
                acc[gi][2] = fmaf(pv, w2, acc[gi][2]);
                acc[gi][3] = fmaf(pv, w3, acc[gi][3]);
            }
        }
        __syncthreads();
    }

    float* Q = (float*)sbuf;
    float b0 = bl1[c0], b1 = bl1[c0 + 1], b2 = bl1[c0 + 2], b3 = bl1[c0 + 3];
    #pragma unroll
    for (int gi = 0; gi < 8; gi++) {
        Q[(g0 + gi) * 64 + c0 + 0] = acc[gi][0] + b0;
        Q[(g0 + gi) * 64 + c0 + 1] = acc[gi][1] + b1;
        Q[(g0 + gi) * 64 + c0 + 2] = acc[gi][2] + b2;
        Q[(g0 + gi) * 64 + c0 + 3] = acc[gi][3] + b3;
    }
    __syncthreads();

    if (t < 128) {
        float dot = bl2[0];
        #pragma unroll 8
        for (int c = 0; c < 64; c++)
            dot = fmaf(Q[t * 64 + c], Wl2[c], dot);
        out[gbase + t] = 1.0f / (1.0f + expf(-dot));
    }
}

// ---------------- launch ----------------
extern "C" void kernel_launch(void* const* d_in, const int* in_sizes, int n_in,
                              void* d_out, int out_size) {
    const float* x   = (const float*)d_in[0];
    const int*   ei  = (const int*)d_in[1];    // int64 in reference -> int32 in harness
    // d_in[2] = batch (unused; structure is implicit)
    const float* W1l = (const float*)d_in[3];
    const float* W1r = (const float*)d_in[4];
    const float* b1  = (const float*)d_in[5];
    const float* W2l = (const float*)d_in[6];
    const float* W2r = (const float*)d_in[7];
    const float* b2  = (const float*)d_in[8];
    const float* Wl1 = (const float*)d_in[9];
    const float* bl1 = (const float*)d_in[10];
    const float* Wl2 = (const float*)d_in[11];
    const float* bl2 = (const float*)d_in[12];

    float* out_scores = (float*)d_out;              // [512]
    float* out_xtrain = (float*)d_out + G_;         // [46080*64]

    const int* src = ei;
    const int* dst = ei + EE;

    // K=90 GEMM needs 57.6 KB dynamic smem (> 48 KB default) — opt in once.
    static bool s_attr_done = false;
    if (!s_attr_done) {
        (void)cudaFuncSetAttribute(gemm_dual<F_IN, false>,
                                   cudaFuncAttributeMaxDynamicSharedMemorySize,
                                   (F_IN * 128 + 32 * F_IN) * 4);
        s_attr_done = true;
    }

    // CSR build
    zero_kernel<<<(NN + 255) / 256, 256>>>();
    count_kernel<<<EE / 256, 256>>>(dst);
    scan_kernel<<<1, 1024>>>();
    fill_kernel<<<EE / 256, 256>>>(src, dst);

    // conv1
    gemm_dual<F_IN, false><<<NN / 128, 256, (F_IN * 128 + 32 * F_IN) * 4>>>(x, W1l, W1r, b1);
    aggregate<true><<<G_, 256>>>(out_xtrain);

    // conv2
    gemm_dual<HH, true><<<NN / 128, 256, (HH * 128 + 32 * HH) * 4>>>(nullptr, W2l, W2r, b2);
    aggregate<false><<<G_, 256>>>(nullptr);

    // pool + MLP
    pool_kernel<<<G_, 256>>>();
    mlp_kernel<<<G_ / 128, 256>>>(Wl1, bl1, Wl2, bl2, out_scores);
}

// round 5
// speedup vs baseline: 2.3582x; 2.3582x over previous
#include <cuda_runtime.h>
#include <cuda_bf16.h>
#include <math.h>

#define G_   512
#define NPG  90
#define NN   (G_ * NPG)      // 46080
#define DEG  20
#define EE   (NN * DEG)      // 921600
#define F_IN 90
#define HH   64
#define KK   70
#define PDIM (KK * HH)       // 4480
#define ECAP 2560            // per-graph edge staging capacity (mean 1800, sd ~42)

// ---------------- device scratch (static, no allocations) ----------------
__device__ float g_t[NN * HH];      // X @ Wl  (message features)
__device__ float g_self[NN * HH];   // X @ Wr + b (self features)
__device__ float g_p[G_ * PDIM];    // pooled features
__device__ int   g_cnt[NN];
__device__ int   g_cur[NN];
__device__ int   g_off[NN + 1];
__device__ int   g_eidx[EE];

// ---------------- CSR build ----------------
__global__ void zero_kernel() {
    int i = blockIdx.x * blockDim.x + threadIdx.x;
    if (i < NN) { g_cnt[i] = 0; g_cur[i] = 0; }
}

__global__ void count_kernel(const int* __restrict__ dst) {
    int e = blockIdx.x * blockDim.x + threadIdx.x;
    if (e < EE) {
        int d = dst[e];
        if ((unsigned)d < NN) atomicAdd(&g_cnt[d], 1);
    }
}

// single block, 1024 threads, 45 elems/thread (46080 = 1024*45)
__global__ void scan_kernel() {
    __shared__ int sums[1024];
    int tid = threadIdx.x;
    int base = tid * 45;
    int run = 0;
    #pragma unroll 5
    for (int i = 0; i < 45; i++) run += g_cnt[base + i];
    sums[tid] = run;
    __syncthreads();
    for (int d = 1; d < 1024; d <<= 1) {
        int v = 0;
        if (tid >= d) v = sums[tid - d];
        __syncthreads();
        if (tid >= d) sums[tid] += v;
        __syncthreads();
    }
    int pre = (tid == 0) ? 0 : sums[tid - 1];
    #pragma unroll 5
    for (int i = 0; i < 45; i++) {
        g_off[base + i] = pre;
        pre += g_cnt[base + i];
    }
    if (tid == 1023) g_off[NN] = pre;
}

__global__ void fill_kernel(const int* __restrict__ src,
                            const int* __restrict__ dst) {
    int e = blockIdx.x * blockDim.x + threadIdx.x;
    if (e < EE) {
        int d = dst[e];
        int s = src[e];
        if ((unsigned)d < NN && (unsigned)s < NN) {
            int p = atomicAdd(&g_cur[d], 1);
            g_eidx[g_off[d] + p] = s;
        }
    }
}

// ---------------- fused dual GEMM: T = X@Wl ; S = X@Wr + b ----------------
// blockDim 256; 128 rows per block (4 passes of 32 rows, 4 rowgroups x 8 rows)
// RELU: apply relu when loading X (used for layer 2 reading x_train)
template <int K, bool RELU>
__global__ void gemm_dual(const float* __restrict__ X,
                          const float* __restrict__ Wl,
                          const float* __restrict__ Wr,
                          const float* __restrict__ bias) {
    extern __shared__ float smem[];
    float* Ws = smem;               // [K][128]
    float* Xs = smem + K * 128;     // [32][K]

    int t = threadIdx.x;
    int c = t & 63;
    int rg = t >> 6;                // 0..3

    for (int idx = t; idx < K * 128; idx += 256) {
        int k = idx >> 7, cc = idx & 127;
        Ws[idx] = (cc < 64) ? Wl[k * 64 + cc] : Wr[k * 64 + (cc - 64)];
    }
    __syncthreads();

    int rowBase = blockIdx.x * 128;
    float bv = bias[c];

    for (int p = 0; p < 4; p++) {
        int r0 = rowBase + p * 32;
        for (int idx = t; idx < 32 * K; idx += 256) {
            int row = idx / K, k = idx - row * K;
            float v = X[(r0 + row) * K + k];
            Xs[row * K + k] = RELU ? fmaxf(v, 0.f) : v;
        }
        __syncthreads();

        float acc0[8], acc1[8];
        #pragma unroll
        for (int i = 0; i < 8; i++) { acc0[i] = 0.f; acc1[i] = 0.f; }

        const float* xb = Xs + (rg * 8) * K;
        #pragma unroll 2
        for (int k = 0; k < K; k++) {
            float w0 = Ws[k * 128 + c];
            float w1 = Ws[k * 128 + 64 + c];
            #pragma unroll
            for (int i = 0; i < 8; i++) {
                float xv = xb[i * K + k];
                acc0[i] = fmaf(xv, w0, acc0[i]);
                acc1[i] = fmaf(xv, w1, acc1[i]);
            }
        }
        #pragma unroll
        for (int i = 0; i < 8; i++) {
            int row = r0 + rg * 8 + i;
            g_t[row * 64 + c]    = acc0[i];
            g_self[row * 64 + c] = acc1[i] + bv;
        }
        __syncthreads();
    }
}

// ---------------- aggregation 1: h1 = mean_csr(t) + self -> x_train ----------------
// block = graph; stages message rows + edge list + offsets in smem
__global__ void aggregate1(float* __restrict__ out_h) {
    __shared__ float ts[NPG * HH];     // 23040 B
    __shared__ int   es[ECAP];         // 10240 B
    __shared__ int   offs[NPG + 1];
    int g = blockIdx.x;
    int base = g * NPG;
    int t = threadIdx.x;

    for (int i = t; i < NPG * HH; i += 256)
        ts[i] = g_t[base * HH + i];
    for (int i = t; i <= NPG; i += 256)
        offs[i] = g_off[base + i];
    __syncthreads();

    int s_begin = offs[0];
    int nedge = offs[NPG] - s_begin;
    int ncap = nedge < ECAP ? nedge : ECAP;
    for (int i = t; i < ncap; i += 256)
        es[i] = g_eidx[s_begin + i] - base;
    __syncthreads();

    int wid = t >> 5, lane = t & 31;
    for (int n = wid; n < NPG; n += 8) {
        int node = base + n;
        int s0 = offs[n], s1 = offs[n + 1];
        float a0 = 0.f, a1 = 0.f;
        for (int j = s0; j < s1; j++) {
            int idx = j - s_begin;
            int sl = (idx < ECAP) ? es[idx] : (g_eidx[j] - base);
            a0 += ts[sl * 64 + lane];
            a1 += ts[sl * 64 + 32 + lane];
        }
        int cnt = s1 - s0;
        float inv = 1.0f / (float)max(cnt, 1);
        out_h[node * 64 + lane]      = fmaf(a0, inv, g_self[node * 64 + lane]);
        out_h[node * 64 + 32 + lane] = fmaf(a1, inv, g_self[node * 64 + 32 + lane]);
    }
}

// ---------------- aggregation 2 + sort-pool fused ----------------
// h2 stays in smem; sort by channel 63 (stable desc), write top-70 rows to g_p
__global__ void aggregate2_pool() {
    extern __shared__ float dyn[];
    float* ts = dyn;                   // [NPG*64]
    float* hs = dyn + NPG * HH;        // [NPG*64]
    int*   es = (int*)(dyn + 2 * NPG * HH);  // [ECAP]
    __shared__ int   offs[NPG + 1];
    __shared__ float key[NPG];
    __shared__ int   order[KK];

    int g = blockIdx.x;
    int base = g * NPG;
    int t = threadIdx.x;

    for (int i = t; i < NPG * HH; i += 256)
        ts[i] = g_t[base * HH + i];
    for (int i = t; i <= NPG; i += 256)
        offs[i] = g_off[base + i];
    __syncthreads();

    int s_begin = offs[0];
    int nedge = offs[NPG] - s_begin;
    int ncap = nedge < ECAP ? nedge : ECAP;
    for (int i = t; i < ncap; i += 256)
        es[i] = g_eidx[s_begin + i] - base;
    __syncthreads();

    int wid = t >> 5, lane = t & 31;
    for (int n = wid; n < NPG; n += 8) {
        int node = base + n;
        int s0 = offs[n], s1 = offs[n + 1];
        float a0 = 0.f, a1 = 0.f;
        for (int j = s0; j < s1; j++) {
            int idx = j - s_begin;
            int sl = (idx < ECAP) ? es[idx] : (g_eidx[j] - base);
            a0 += ts[sl * 64 + lane];
            a1 += ts[sl * 64 + 32 + lane];
        }
        int cnt = s1 - s0;
        float inv = 1.0f / (float)max(cnt, 1);
        hs[n * 64 + lane]      = fmaf(a0, inv, g_self[node * 64 + lane]);
        hs[n * 64 + 32 + lane] = fmaf(a1, inv, g_self[node * 64 + 32 + lane]);
    }
    __syncthreads();

    if (t < NPG) key[t] = hs[t * 64 + 63];
    __syncthreads();
    if (t < NPG) {
        float kv = key[t];
        int rank = 0;
        #pragma unroll 6
        for (int j = 0; j < NPG; j++) {
            float kj = key[j];
            rank += (kj > kv) || (kj == kv && j < t);
        }
        if (rank < KK) order[rank] = t;
    }
    __syncthreads();
    for (int idx = t; idx < PDIM; idx += 256) {
        int r = idx >> 6, f = idx & 63;
        g_p[g * PDIM + idx] = hs[order[r] * 64 + f];
    }
}

// ---------------- MLP: P[512,4480]@Wl1[4480,64]+bl1 -> @Wl2+bl2 -> sigmoid ----------------
// 128 blocks x 4 graphs; 256 threads: c = t&63 (col), q = t>>6 (K-quarter of chunk)
// K streamed in chunks of 128 (W chunk 32KB smem); P staged transposed for float4
#define MLP_GPB 4
#define KCH 128
__global__ void mlp_kernel(const float* __restrict__ Wl1,
                           const float* __restrict__ bl1,
                           const float* __restrict__ Wl2,
                           const float* __restrict__ bl2,
                           float* __restrict__ out) {
    __shared__ float Ws[KCH * 64];          // 32 KB
    __shared__ float Ps[KCH * MLP_GPB];     // 2 KB, [kk][g]
    __shared__ float red[4 * MLP_GPB * 64]; // 4 KB

    int t = threadIdx.x;
    int c = t & 63;
    int q = t >> 6;      // 0..3
    int gbase = blockIdx.x * MLP_GPB;

    float acc[MLP_GPB];
    #pragma unroll
    for (int i = 0; i < MLP_GPB; i++) acc[i] = 0.f;

    for (int k0 = 0; k0 < PDIM; k0 += KCH) {
        for (int idx = t; idx < KCH * 64; idx += 256)
            Ws[idx] = Wl1[(k0 + (idx >> 6)) * 64 + (idx & 63)];
        for (int idx = t; idx < KCH * MLP_GPB; idx += 256) {
            int kk = idx >> 2, gg = idx & 3;
            Ps[kk * MLP_GPB + gg] = g_p[(gbase + gg) * PDIM + k0 + kk];
        }
        __syncthreads();

        int kb = q * (KCH / 4);
        #pragma unroll 8
        for (int kk = 0; kk < KCH / 4; kk++) {
            int k = kb + kk;
            float w = Ws[k * 64 + c];
            float4 pv = *(const float4*)&Ps[k * MLP_GPB];
            acc[0] = fmaf(pv.x, w, acc[0]);
            acc[1] = fmaf(pv.y, w, acc[1]);
            acc[2] = fmaf(pv.z, w, acc[2]);
            acc[3] = fmaf(pv.w, w, acc[3]);
        }
        __syncthreads();
    }

    // cross-quarter reduction
    #pragma unroll
    for (int gg = 0; gg < MLP_GPB; gg++)
        red[(q * MLP_GPB + gg) * 64 + c] = acc[gg];
    __syncthreads();

    // t in [0,256): gg = t>>6, c = t&63 — sum 4 quarters, bias, second linear
    {
        int gg = t >> 6;
        float s = red[(0 * MLP_GPB + gg) * 64 + c]
                + red[(1 * MLP_GPB + gg) * 64 + c]
                + red[(2 * MLP_GPB + gg) * 64 + c]
                + red[(3 * MLP_GPB + gg) * 64 + c];
        s += bl1[c];
        __syncthreads();
        red[gg * 64 + c] = s * Wl2[c];
    }
    __syncthreads();

    if (t < MLP_GPB) {
        float dot = bl2[0];
        #pragma unroll 8
        for (int cc = 0; cc < 64; cc++)
            dot += red[t * 64 + cc];
        out[gbase + t] = 1.0f / (1.0f + expf(-dot));
    }
}

// ---------------- launch ----------------
extern "C" void kernel_launch(void* const* d_in, const int* in_sizes, int n_in,
                              void* d_out, int out_size) {
    const float* x   = (const float*)d_in[0];
    const int*   ei  = (const int*)d_in[1];    // int64 in reference -> int32 in harness
    const float* W1l = (const float*)d_in[3];
    const float* W1r = (const float*)d_in[4];
    const float* b1  = (const float*)d_in[5];
    const float* W2l = (const float*)d_in[6];
    const float* W2r = (const float*)d_in[7];
    const float* b2  = (const float*)d_in[8];
    const float* Wl1 = (const float*)d_in[9];
    const float* bl1 = (const float*)d_in[10];
    const float* Wl2 = (const float*)d_in[11];
    const float* bl2 = (const float*)d_in[12];

    float* out_scores = (float*)d_out;              // [512]
    float* out_xtrain = (float*)d_out + G_;         // [46080*64]

    const int* src = ei;
    const int* dst = ei + EE;

    static bool s_attr_done = false;
    if (!s_attr_done) {
        (void)cudaFuncSetAttribute(gemm_dual<F_IN, false>,
                                   cudaFuncAttributeMaxDynamicSharedMemorySize,
                                   (F_IN * 128 + 32 * F_IN) * 4);
        (void)cudaFuncSetAttribute(aggregate2_pool,
                                   cudaFuncAttributeMaxDynamicSharedMemorySize,
                                   (2 * NPG * HH) * 4 + ECAP * 4);
        s_attr_done = true;
    }

    // CSR build
    zero_kernel<<<(NN + 255) / 256, 256>>>();
    count_kernel<<<EE / 256, 256>>>(dst);
    scan_kernel<<<1, 1024>>>();
    fill_kernel<<<EE / 256, 256>>>(src, dst);

    // conv1: gemm + aggregate (h1 -> x_train output region)
    gemm_dual<F_IN, false><<<NN / 128, 256, (F_IN * 128 + 32 * F_IN) * 4>>>(x, W1l, W1r, b1);
    aggregate1<<<G_, 256>>>(out_xtrain);

    // conv2: gemm reads x_train with relu-on-load; aggregate fused with sort-pool
    gemm_dual<HH, true><<<NN / 128, 256, (HH * 128 + 32 * HH) * 4>>>(out_xtrain, W2l, W2r, b2);
    aggregate2_pool<<<G_, 256, (2 * NPG * HH) * 4 + ECAP * 4>>>();

    // MLP head
    mlp_kernel<<<G_ / MLP_GPB, 256>>>(Wl1, bl1, Wl2, bl2, out_scores);
}